// round 3
// baseline (speedup 1.0000x reference)
#include <cuda_runtime.h>

// ---------------------------------------------------------------------------
// SelfAttention2d: N=16, C=512, H=W=64, C_BAR=64, C_HAT=256
// Decomposition:
//   1. pack  W_all[384,512] = [w_theta; w_phi; w_g]
//   2. proj[n,384,4096] = W_all @ x_n          (NN GEMM)
//   3. pool rows 64..383 -> phi_p[64,1024], g_p[256,1024]
//   4. scores[n,4096,1024] = theta^T @ phi_p   (TN GEMM, K=64)
//   5. softmax rows
//   6. y[n,256,4096] = g_p @ attn^T            (NT GEMM, K=1024)
//   7. out = gamma * (w_o @ y) + x             (NN GEMM + epilogue)
// ---------------------------------------------------------------------------

#define NB    16
#define C_IN  512
#define HWX   4096
#define HW4   1024
#define CBAR  64
#define CHAT  256
#define MPROJ 384   // 64 + 64 + 256

// Scratch (static device globals; no allocation at launch time)
__device__ float g_Wall[MPROJ * C_IN];                       //  0.8 MB
__device__ float g_proj[(size_t)NB * MPROJ * HWX];           // 100.7 MB
__device__ float g_phi [(size_t)NB * CBAR * HW4];            //   4.2 MB
__device__ float g_g   [(size_t)NB * CHAT * HW4];            //  16.8 MB
__device__ float g_scores[(size_t)NB * HWX * HW4];           // 268.4 MB
__device__ float g_y   [(size_t)NB * CHAT * HWX];            //  67.1 MB

// ---------------------------------------------------------------------------
// Pack the three projection weights into one [384,512] matrix
// ---------------------------------------------------------------------------
__global__ void pack_w_kernel(const float* __restrict__ wt,
                              const float* __restrict__ wp,
                              const float* __restrict__ wg)
{
    int i = blockIdx.x * blockDim.x + threadIdx.x;
    if (i >= MPROJ * C_IN) return;
    const int T = 64 * C_IN;    // theta block
    const int P = 128 * C_IN;   // theta+phi
    float v;
    if (i < T)       v = wt[i];
    else if (i < P)  v = wp[i - T];
    else             v = wg[i - P];
    g_Wall[i] = v;
}

// ---------------------------------------------------------------------------
// NN GEMM: C[m,n] = sum_k A[m,k] * B[k,n]   (A shared across batch)
// 128x128 tile, BK=8, 256 threads, 8x8 per thread.
// EPI=1: C = gamma * C + resid (residual add, gamma read from device mem)
// ---------------------------------------------------------------------------
template<int EPI>
__global__ __launch_bounds__(256) void gemm_nn_t(
    const float* __restrict__ A,     // [M,K]
    const float* __restrict__ B,     // per-batch [K,N]
    float* __restrict__ C,           // per-batch [M,N]
    int M, int N, int K,
    long sB, long sC,
    const float* __restrict__ gammaPtr,
    const float* __restrict__ resid, long sR)
{
    const int BM = 128, BN = 128, BK = 8;
    __shared__ float As[BK][BM];
    __shared__ float Bs[BK][BN];

    int b  = blockIdx.z;
    const float* Bp = B + (long)b * sB;
    float*       Cp = C + (long)b * sC;

    int m0 = blockIdx.y * BM;
    int n0 = blockIdx.x * BN;
    int tid = threadIdx.x;

    int aRow = tid >> 1;           // 0..127
    int aCol = (tid & 1) << 2;     // 0 or 4
    int bRow = tid >> 5;           // 0..7
    int bCol = (tid & 31) << 2;    // 0..124

    int trow = (tid >> 4) << 3;    // 0..120 step 8
    int tcol = (tid & 15) << 3;

    float acc[8][8];
#pragma unroll
    for (int i = 0; i < 8; i++)
#pragma unroll
        for (int j = 0; j < 8; j++) acc[i][j] = 0.f;

    const float* Aptr = A  + (long)(m0 + aRow) * K + aCol;
    const float* Bptr = Bp + (long)bRow * N + n0 + bCol;

    for (int k0 = 0; k0 < K; k0 += BK) {
        float4 av = *(const float4*)(Aptr + k0);
        float4 bv = *(const float4*)(Bptr + (long)k0 * N);
        As[aCol + 0][aRow] = av.x;
        As[aCol + 1][aRow] = av.y;
        As[aCol + 2][aRow] = av.z;
        As[aCol + 3][aRow] = av.w;
        *(float4*)&Bs[bRow][bCol] = bv;
        __syncthreads();
#pragma unroll
        for (int kk = 0; kk < BK; kk++) {
            float a[8], bb[8];
            *(float4*)&a[0]  = *(const float4*)&As[kk][trow];
            *(float4*)&a[4]  = *(const float4*)&As[kk][trow + 4];
            *(float4*)&bb[0] = *(const float4*)&Bs[kk][tcol];
            *(float4*)&bb[4] = *(const float4*)&Bs[kk][tcol + 4];
#pragma unroll
            for (int i = 0; i < 8; i++)
#pragma unroll
                for (int j = 0; j < 8; j++)
                    acc[i][j] = fmaf(a[i], bb[j], acc[i][j]);
        }
        __syncthreads();
    }

    float gam = 0.f;
    const float* Rp = nullptr;
    if (EPI) {
        gam = gammaPtr[0];
        Rp  = resid + (long)b * sR;
    }

#pragma unroll
    for (int i = 0; i < 8; i++) {
        long row = m0 + trow + i;
#pragma unroll
        for (int j = 0; j < 8; j += 4) {
            long off = row * (long)N + n0 + tcol + j;
            float4 v = make_float4(acc[i][j], acc[i][j+1], acc[i][j+2], acc[i][j+3]);
            if (EPI) {
                float4 r = *(const float4*)(Rp + off);
                v.x = fmaf(gam, v.x, r.x);
                v.y = fmaf(gam, v.y, r.y);
                v.z = fmaf(gam, v.z, r.z);
                v.w = fmaf(gam, v.w, r.w);
            }
            *(float4*)(Cp + off) = v;
        }
    }
}

// ---------------------------------------------------------------------------
// TN GEMM: C[m,n] = sum_k A[k,m] * B[k,n]   (both k-major -> direct loads)
// Used for scores = theta^T @ phi  (M=4096, N=1024, K=64)
// ---------------------------------------------------------------------------
__global__ __launch_bounds__(256) void gemm_tn(
    const float* __restrict__ A,  // per-batch, element (k,m) at k*lda + m
    const float* __restrict__ B,  // per-batch, element (k,n) at k*ldb + n
    float* __restrict__ C,        // per-batch [M,N]
    int M, int N, int K, int lda, int ldb,
    long sA, long sB, long sC)
{
    const int BM = 128, BN = 128, BK = 8;
    __shared__ float As[BK][BM];
    __shared__ float Bs[BK][BN];

    int b = blockIdx.z;
    const float* Ap = A + (long)b * sA;
    const float* Bp = B + (long)b * sB;
    float*       Cp = C + (long)b * sC;

    int m0 = blockIdx.y * BM;
    int n0 = blockIdx.x * BN;
    int tid = threadIdx.x;

    int r = tid >> 5;            // 0..7
    int c = (tid & 31) << 2;     // 0..124
    int trow = (tid >> 4) << 3;
    int tcol = (tid & 15) << 3;

    float acc[8][8];
#pragma unroll
    for (int i = 0; i < 8; i++)
#pragma unroll
        for (int j = 0; j < 8; j++) acc[i][j] = 0.f;

    for (int k0 = 0; k0 < K; k0 += BK) {
        float4 av = *(const float4*)(Ap + (long)(k0 + r) * lda + m0 + c);
        float4 bv = *(const float4*)(Bp + (long)(k0 + r) * ldb + n0 + c);
        *(float4*)&As[r][c] = av;
        *(float4*)&Bs[r][c] = bv;
        __syncthreads();
#pragma unroll
        for (int kk = 0; kk < BK; kk++) {
            float a[8], bb[8];
            *(float4*)&a[0]  = *(const float4*)&As[kk][trow];
            *(float4*)&a[4]  = *(const float4*)&As[kk][trow + 4];
            *(float4*)&bb[0] = *(const float4*)&Bs[kk][tcol];
            *(float4*)&bb[4] = *(const float4*)&Bs[kk][tcol + 4];
#pragma unroll
            for (int i = 0; i < 8; i++)
#pragma unroll
                for (int j = 0; j < 8; j++)
                    acc[i][j] = fmaf(a[i], bb[j], acc[i][j]);
        }
        __syncthreads();
    }

#pragma unroll
    for (int i = 0; i < 8; i++) {
        long row = m0 + trow + i;
#pragma unroll
        for (int j = 0; j < 8; j += 4) {
            long off = row * (long)N + n0 + tcol + j;
            *(float4*)(Cp + off) =
                make_float4(acc[i][j], acc[i][j+1], acc[i][j+2], acc[i][j+3]);
        }
    }
}

// ---------------------------------------------------------------------------
// NT GEMM: C[m,n] = sum_k A[m,k] * B[n,k]   (both row-major over k)
// Used for y = g_p @ attn^T  (M=256, N=4096, K=1024)
// ---------------------------------------------------------------------------
__global__ __launch_bounds__(256) void gemm_nt(
    const float* __restrict__ A,  // per-batch [M,K]
    const float* __restrict__ B,  // per-batch [N,K]
    float* __restrict__ C,        // per-batch [M,N]
    int M, int N, int K,
    long sA, long sB, long sC)
{
    const int BM = 128, BN = 128, BK = 8;
    __shared__ float As[BK][BM];
    __shared__ float Bs[BK][BN];

    int b = blockIdx.z;
    const float* Ap = A + (long)b * sA;
    const float* Bp = B + (long)b * sB;
    float*       Cp = C + (long)b * sC;

    int m0 = blockIdx.y * BM;
    int n0 = blockIdx.x * BN;
    int tid = threadIdx.x;

    int row = tid >> 1;          // 0..127
    int col = (tid & 1) << 2;    // 0 or 4
    int trow = (tid >> 4) << 3;
    int tcol = (tid & 15) << 3;

    float acc[8][8];
#pragma unroll
    for (int i = 0; i < 8; i++)
#pragma unroll
        for (int j = 0; j < 8; j++) acc[i][j] = 0.f;

    const float* Aptr = Ap + (long)(m0 + row) * K + col;
    const float* Bptr = Bp + (long)(n0 + row) * K + col;

    for (int k0 = 0; k0 < K; k0 += BK) {
        float4 av = *(const float4*)(Aptr + k0);
        float4 bv = *(const float4*)(Bptr + k0);
        As[col + 0][row] = av.x;
        As[col + 1][row] = av.y;
        As[col + 2][row] = av.z;
        As[col + 3][row] = av.w;
        Bs[col + 0][row] = bv.x;
        Bs[col + 1][row] = bv.y;
        Bs[col + 2][row] = bv.z;
        Bs[col + 3][row] = bv.w;
        __syncthreads();
#pragma unroll
        for (int kk = 0; kk < BK; kk++) {
            float a[8], bb[8];
            *(float4*)&a[0]  = *(const float4*)&As[kk][trow];
            *(float4*)&a[4]  = *(const float4*)&As[kk][trow + 4];
            *(float4*)&bb[0] = *(const float4*)&Bs[kk][tcol];
            *(float4*)&bb[4] = *(const float4*)&Bs[kk][tcol + 4];
#pragma unroll
            for (int i = 0; i < 8; i++)
#pragma unroll
                for (int j = 0; j < 8; j++)
                    acc[i][j] = fmaf(a[i], bb[j], acc[i][j]);
        }
        __syncthreads();
    }

#pragma unroll
    for (int i = 0; i < 8; i++) {
        long row_g = m0 + trow + i;
#pragma unroll
        for (int j = 0; j < 8; j += 4) {
            long off = row_g * (long)N + n0 + tcol + j;
            *(float4*)(Cp + off) =
                make_float4(acc[i][j], acc[i][j+1], acc[i][j+2], acc[i][j+3]);
        }
    }
}

// ---------------------------------------------------------------------------
// 2x2 max pool of proj rows 64..383 into phi_p / g_p
// ---------------------------------------------------------------------------
__global__ void pool_kernel()
{
    long idx = (long)blockIdx.x * blockDim.x + threadIdx.x;
    const long total = (long)NB * 320 * HW4;
    if (idx >= total) return;
    int  tp = (int)(idx & (HW4 - 1));
    long rest = idx >> 10;
    int  ch = (int)(rest % 320);
    int  b  = (int)(rest / 320);
    int  ph = tp >> 5, pw = tp & 31;

    int srcRow = (ch < CBAR) ? (64 + ch) : (128 + (ch - CBAR));
    const float* src = g_proj + (long)b * MPROJ * HWX
                              + (long)srcRow * HWX
                              + (2 * ph) * 64 + 2 * pw;
    float m = fmaxf(fmaxf(src[0], src[1]), fmaxf(src[64], src[65]));

    if (ch < CBAR)
        g_phi[((long)b * CBAR + ch) * HW4 + tp] = m;
    else
        g_g[((long)b * CHAT + (ch - CBAR)) * HW4 + tp] = m;
}

// ---------------------------------------------------------------------------
// Rowwise softmax over 1024 elements, in place on g_scores. 1 block/row.
// ---------------------------------------------------------------------------
__global__ __launch_bounds__(128) void softmax_kernel()
{
    long row = blockIdx.x;
    float4* p = ((float4*)g_scores) + row * (HW4 / 4);
    int tid  = threadIdx.x;
    int wid  = tid >> 5, lane = tid & 31;

    float4 v0 = p[tid];
    float4 v1 = p[tid + 128];

    float mx = fmaxf(fmaxf(fmaxf(v0.x, v0.y), fmaxf(v0.z, v0.w)),
                     fmaxf(fmaxf(v1.x, v1.y), fmaxf(v1.z, v1.w)));
#pragma unroll
    for (int o = 16; o > 0; o >>= 1)
        mx = fmaxf(mx, __shfl_xor_sync(0xffffffffu, mx, o));

    __shared__ float redm[4];
    __shared__ float reds[4];
    if (lane == 0) redm[wid] = mx;
    __syncthreads();
    mx = fmaxf(fmaxf(redm[0], redm[1]), fmaxf(redm[2], redm[3]));

    v0.x = __expf(v0.x - mx); v0.y = __expf(v0.y - mx);
    v0.z = __expf(v0.z - mx); v0.w = __expf(v0.w - mx);
    v1.x = __expf(v1.x - mx); v1.y = __expf(v1.y - mx);
    v1.z = __expf(v1.z - mx); v1.w = __expf(v1.w - mx);

    float s = v0.x + v0.y + v0.z + v0.w + v1.x + v1.y + v1.z + v1.w;
#pragma unroll
    for (int o = 16; o > 0; o >>= 1)
        s += __shfl_xor_sync(0xffffffffu, s, o);
    if (lane == 0) reds[wid] = s;
    __syncthreads();
    s = reds[0] + reds[1] + reds[2] + reds[3];

    float inv = 1.0f / s;
    v0.x *= inv; v0.y *= inv; v0.z *= inv; v0.w *= inv;
    v1.x *= inv; v1.y *= inv; v1.z *= inv; v1.w *= inv;
    p[tid]       = v0;
    p[tid + 128] = v1;
}

// ---------------------------------------------------------------------------
// Launch
// ---------------------------------------------------------------------------
extern "C" void kernel_launch(void* const* d_in, const int* in_sizes, int n_in,
                              void* d_out, int out_size)
{
    const float* x       = (const float*)d_in[0];
    const float* w_theta = (const float*)d_in[1];
    const float* w_phi   = (const float*)d_in[2];
    const float* w_g     = (const float*)d_in[3];
    const float* w_o     = (const float*)d_in[4];
    const float* gamma   = (const float*)d_in[5];
    float* out = (float*)d_out;

    float *pWall, *pProj, *pPhi, *pG, *pScores, *pY;
    cudaGetSymbolAddress((void**)&pWall,   g_Wall);
    cudaGetSymbolAddress((void**)&pProj,   g_proj);
    cudaGetSymbolAddress((void**)&pPhi,    g_phi);
    cudaGetSymbolAddress((void**)&pG,      g_g);
    cudaGetSymbolAddress((void**)&pScores, g_scores);
    cudaGetSymbolAddress((void**)&pY,      g_y);

    // 1. pack weights
    pack_w_kernel<<<(MPROJ * C_IN + 255) / 256, 256>>>(w_theta, w_phi, w_g);

    // 2. proj = W_all @ x  : M=384, N=4096, K=512
    {
        dim3 grid(HWX / 128, MPROJ / 128, NB);
        gemm_nn_t<0><<<grid, 256>>>(pWall, x, pProj,
                                    MPROJ, HWX, C_IN,
                                    (long)C_IN * HWX, (long)MPROJ * HWX,
                                    nullptr, nullptr, 0);
    }

    // 3. pool phi & g
    {
        long total = (long)NB * 320 * HW4;
        pool_kernel<<<(unsigned)((total + 255) / 256), 256>>>();
    }

    // 4. scores = theta^T @ phi_p : M=4096, N=1024, K=64
    {
        dim3 grid(HW4 / 128, HWX / 128, NB);
        gemm_tn<<<grid, 256>>>(pProj, pPhi, pScores,
                               HWX, HW4, CBAR,
                               HWX, HW4,
                               (long)MPROJ * HWX, (long)CBAR * HW4,
                               (long)HWX * HW4);
    }

    // 5. softmax rows
    softmax_kernel<<<NB * HWX, 128>>>();

    // 6. y = g_p @ attn^T : M=256, N=4096, K=1024
    {
        dim3 grid(HWX / 128, CHAT / 128, NB);
        gemm_nt<<<grid, 256>>>(pG, pScores, pY,
                               CHAT, HWX, HW4,
                               (long)CHAT * HW4, (long)HWX * HW4,
                               (long)CHAT * HWX);
    }

    // 7. out = gamma * (w_o @ y) + x : M=512, N=4096, K=256
    {
        dim3 grid(HWX / 128, C_IN / 128, NB);
        gemm_nn_t<1><<<grid, 256>>>(w_o, pY, out,
                                    C_IN, HWX, CHAT,
                                    (long)CHAT * HWX, (long)C_IN * HWX,
                                    gamma, x, (long)C_IN * HWX);
    }
}

// round 4
// speedup vs baseline: 2.6485x; 2.6485x over previous
#include <cuda_runtime.h>

// ---------------------------------------------------------------------------
// SelfAttention2d: N=16, C=512, H=W=64, C_BAR=64, C_HAT=256
// Round 3: all GEMMs on tf32 tensor cores (mma.sync.m16n8k8).
//   1. pack  W_all[384,512] = [w_theta; w_phi; w_g]
//   2. proj[n,384,4096] = W_all @ x_n          (A:N  B:N)
//   3. pool rows 64..383 -> phi_p[64,1024], g_p[256,1024]
//   4. scores[n,4096,1024] = theta^T @ phi_p   (A:T  B:N, K=64)
//   5. softmax rows
//   6. y[n,256,4096] = g_p @ attn^T            (A:N  B:T, K=1024)
//   7. out = gamma * (w_o @ y) + x             (A:N  B:N + epilogue)
// ---------------------------------------------------------------------------

#define NB    16
#define C_IN  512
#define HWX   4096
#define HW4   1024
#define CBAR  64
#define CHAT  256
#define MPROJ 384

#define BM 128
#define BN 128
#define BK 16
#define ASTR 20     // A smem row stride (floats): conflict-free frag loads
#define BSTR 136    // B smem row stride (floats)

// Scratch (static device globals; no allocation at launch time)
__device__ float g_Wall[MPROJ * C_IN];
__device__ float g_proj[(size_t)NB * MPROJ * HWX];
__device__ float g_phi [(size_t)NB * CBAR * HW4];
__device__ float g_g   [(size_t)NB * CHAT * HW4];
__device__ float g_scores[(size_t)NB * HWX * HW4];
__device__ float g_y   [(size_t)NB * CHAT * HWX];

// ---------------------------------------------------------------------------
__device__ __forceinline__ unsigned f2tf(float f) {
    unsigned u;
    asm("cvt.rna.tf32.f32 %0, %1;" : "=r"(u) : "f"(f));
    return u;
}
__device__ __forceinline__ uint4 f2tf4(float4 v) {
    uint4 r; r.x = f2tf(v.x); r.y = f2tf(v.y); r.z = f2tf(v.z); r.w = f2tf(v.w);
    return r;
}
__device__ __forceinline__ void mma_tf32(float d[4], const unsigned a[4],
                                         const unsigned b[2]) {
    asm volatile(
        "mma.sync.aligned.m16n8k8.row.col.f32.tf32.tf32.f32 "
        "{%0,%1,%2,%3}, {%4,%5,%6,%7}, {%8,%9}, {%0,%1,%2,%3};\n"
        : "+f"(d[0]), "+f"(d[1]), "+f"(d[2]), "+f"(d[3])
        : "r"(a[0]), "r"(a[1]), "r"(a[2]), "r"(a[3]), "r"(b[0]), "r"(b[1]));
}

// ---------------------------------------------------------------------------
// Templated tf32 GEMM: C[m,n] = sum_k A(m,k) * B(k,n)
//   LAYA=0: A row-major [M,K] (lda=K).  LAYA=1: A k-major [K,M] (lda=ldM).
//   LAYB=0: B k-major [K,N] (ldb=N).    LAYB=1: B row-major [N,K] (ldb=K).
//   EPI=1 : C = gamma*C + resid
// M, N multiples of 128; K multiple of 16.
// ---------------------------------------------------------------------------
template<int LAYA, int LAYB, int EPI>
__global__ __launch_bounds__(256, 2) void gemm_tc(
    const float* __restrict__ A, const float* __restrict__ B,
    float* __restrict__ C,
    int N, int K, int lda, int ldb,
    long sA, long sB, long sC,
    const float* __restrict__ gammaPtr,
    const float* __restrict__ resid, long sR)
{
    __shared__ __align__(16) unsigned As[2][BM][ASTR];
    __shared__ __align__(16) unsigned Bs[2][BK][BSTR];

    const int tid  = threadIdx.x;
    const int lane = tid & 31;
    const int warp = tid >> 5;
    const int g    = lane >> 2;
    const int tig  = lane & 3;
    const int wm   = (warp & 1) * 64;
    const int wn   = (warp >> 1) * 32;

    const int b  = blockIdx.z;
    const int m0 = blockIdx.y * BM;
    const int n0 = blockIdx.x * BN;

    const float* Ap = A + (long)b * sA;
    const float* Bp = B + (long)b * sB;
    float*       Cp = C + (long)b * sC;

    float acc[4][4][4];
#pragma unroll
    for (int i = 0; i < 4; i++)
#pragma unroll
        for (int j = 0; j < 4; j++)
#pragma unroll
            for (int r = 0; r < 4; r++) acc[i][j][r] = 0.f;

    float4 ra0, ra1, rb0, rb1;

    auto loadA = [&](int k0) {
        if (LAYA == 0) {
            int m = tid >> 2, kq = (tid & 3) << 2;
            ra0 = *(const float4*)(Ap + (long)(m0 + m)      * lda + k0 + kq);
            ra1 = *(const float4*)(Ap + (long)(m0 + m + 64) * lda + k0 + kq);
        } else {
            int k = tid & 7, mq = (tid >> 3) << 2;
            ra0 = *(const float4*)(Ap + (long)(k0 + k)     * lda + m0 + mq);
            ra1 = *(const float4*)(Ap + (long)(k0 + k + 8) * lda + m0 + mq);
        }
    };
    auto loadB = [&](int k0) {
        if (LAYB == 0) {
            int k = tid >> 5, n = (tid & 31) << 2;
            rb0 = *(const float4*)(Bp + (long)(k0 + k)     * ldb + n0 + n);
            rb1 = *(const float4*)(Bp + (long)(k0 + k + 8) * ldb + n0 + n);
        } else {
            int n = tid >> 2, kq = (tid & 3) << 2;
            rb0 = *(const float4*)(Bp + (long)(n0 + n)      * ldb + k0 + kq);
            rb1 = *(const float4*)(Bp + (long)(n0 + n + 64) * ldb + k0 + kq);
        }
    };
    auto storeAB = [&](int buf) {
        if (LAYA == 0) {
            int m = tid >> 2, kq = (tid & 3) << 2;
            *(uint4*)&As[buf][m][kq]      = f2tf4(ra0);
            *(uint4*)&As[buf][m + 64][kq] = f2tf4(ra1);
        } else {
            int k = tid & 7, mq = (tid >> 3) << 2;
            As[buf][mq + 0][k] = f2tf(ra0.x);
            As[buf][mq + 1][k] = f2tf(ra0.y);
            As[buf][mq + 2][k] = f2tf(ra0.z);
            As[buf][mq + 3][k] = f2tf(ra0.w);
            As[buf][mq + 0][k + 8] = f2tf(ra1.x);
            As[buf][mq + 1][k + 8] = f2tf(ra1.y);
            As[buf][mq + 2][k + 8] = f2tf(ra1.z);
            As[buf][mq + 3][k + 8] = f2tf(ra1.w);
        }
        if (LAYB == 0) {
            int k = tid >> 5, n = (tid & 31) << 2;
            int s0 = ((k >> 2) & 3) << 3;
            int s1 = (((k + 8) >> 2) & 3) << 3;
            *(uint4*)&Bs[buf][k][n ^ s0]     = f2tf4(rb0);
            *(uint4*)&Bs[buf][k + 8][n ^ s1] = f2tf4(rb1);
        } else {
            int n = tid >> 2, q = tid & 3;
            int s  = q << 3;            // swizzle for rows 4q..4q+3
            int c0 = n ^ s, c1 = (n + 64) ^ s;
            Bs[buf][4 * q + 0][c0] = f2tf(rb0.x);
            Bs[buf][4 * q + 1][c0] = f2tf(rb0.y);
            Bs[buf][4 * q + 2][c0] = f2tf(rb0.z);
            Bs[buf][4 * q + 3][c0] = f2tf(rb0.w);
            Bs[buf][4 * q + 0][c1] = f2tf(rb1.x);
            Bs[buf][4 * q + 1][c1] = f2tf(rb1.y);
            Bs[buf][4 * q + 2][c1] = f2tf(rb1.z);
            Bs[buf][4 * q + 3][c1] = f2tf(rb1.w);
        }
    };
    auto compute = [&](int buf) {
#pragma unroll
        for (int ks = 0; ks < BK; ks += 8) {
            unsigned af[4][4], bf[4][2];
            const int s0 = ((ks >> 2) & 3) << 3;
            const int s1 = (((ks >> 2) + 1) & 3) << 3;
#pragma unroll
            for (int mi = 0; mi < 4; mi++) {
                int m = wm + mi * 16;
                af[mi][0] = As[buf][m + g]    [ks + tig];
                af[mi][1] = As[buf][m + g + 8][ks + tig];
                af[mi][2] = As[buf][m + g]    [ks + tig + 4];
                af[mi][3] = As[buf][m + g + 8][ks + tig + 4];
            }
#pragma unroll
            for (int ni = 0; ni < 4; ni++) {
                int n = wn + ni * 8 + g;
                bf[ni][0] = Bs[buf][ks + tig]    [n ^ s0];
                bf[ni][1] = Bs[buf][ks + tig + 4][n ^ s1];
            }
#pragma unroll
            for (int mi = 0; mi < 4; mi++)
#pragma unroll
                for (int ni = 0; ni < 4; ni++)
                    mma_tf32(acc[mi][ni], af[mi], bf[ni]);
        }
    };

    const int nt = K / BK;
    loadA(0); loadB(0);
    storeAB(0);
    __syncthreads();
#pragma unroll 1
    for (int t = 0; t < nt; t++) {
        if (t + 1 < nt) { loadA((t + 1) * BK); loadB((t + 1) * BK); }
        compute(t & 1);
        if (t + 1 < nt) storeAB((t + 1) & 1);
        __syncthreads();
    }

    float gam = 0.f;
    const float* Rp = nullptr;
    if (EPI) { gam = gammaPtr[0]; Rp = resid + (long)b * sR; }

#pragma unroll
    for (int mi = 0; mi < 4; mi++) {
#pragma unroll
        for (int ni = 0; ni < 4; ni++) {
            int m = m0 + wm + mi * 16 + g;
            int n = n0 + wn + ni * 8 + 2 * tig;
            float2 v0 = make_float2(acc[mi][ni][0], acc[mi][ni][1]);
            float2 v1 = make_float2(acc[mi][ni][2], acc[mi][ni][3]);
            if (EPI) {
                float2 r0 = *(const float2*)(Rp + (long)m * N + n);
                float2 r1 = *(const float2*)(Rp + (long)(m + 8) * N + n);
                v0.x = fmaf(gam, v0.x, r0.x);
                v0.y = fmaf(gam, v0.y, r0.y);
                v1.x = fmaf(gam, v1.x, r1.x);
                v1.y = fmaf(gam, v1.y, r1.y);
            }
            *(float2*)(Cp + (long)m * N + n)       = v0;
            *(float2*)(Cp + (long)(m + 8) * N + n) = v1;
        }
    }
}

// ---------------------------------------------------------------------------
// Pack the three projection weights into one [384,512] matrix
// ---------------------------------------------------------------------------
__global__ void pack_w_kernel(const float* __restrict__ wt,
                              const float* __restrict__ wp,
                              const float* __restrict__ wg)
{
    int i = blockIdx.x * blockDim.x + threadIdx.x;
    if (i >= MPROJ * C_IN) return;
    const int T = 64 * C_IN;
    const int P = 128 * C_IN;
    float v;
    if (i < T)       v = wt[i];
    else if (i < P)  v = wp[i - T];
    else             v = wg[i - P];
    g_Wall[i] = v;
}

// ---------------------------------------------------------------------------
// 2x2 max pool of proj rows 64..383 into phi_p / g_p
// ---------------------------------------------------------------------------
__global__ void pool_kernel()
{
    long idx = (long)blockIdx.x * blockDim.x + threadIdx.x;
    const long total = (long)NB * 320 * HW4;
    if (idx >= total) return;
    int  tp = (int)(idx & (HW4 - 1));
    long rest = idx >> 10;
    int  ch = (int)(rest % 320);
    int  b  = (int)(rest / 320);
    int  ph = tp >> 5, pw = tp & 31;

    int srcRow = (ch < CBAR) ? (64 + ch) : (128 + (ch - CBAR));
    const float* src = g_proj + (long)b * MPROJ * HWX
                              + (long)srcRow * HWX
                              + (2 * ph) * 64 + 2 * pw;
    float m = fmaxf(fmaxf(src[0], src[1]), fmaxf(src[64], src[65]));

    if (ch < CBAR)
        g_phi[((long)b * CBAR + ch) * HW4 + tp] = m;
    else
        g_g[((long)b * CHAT + (ch - CBAR)) * HW4 + tp] = m;
}

// ---------------------------------------------------------------------------
// Rowwise softmax over 1024 elements, in place on g_scores. 1 block/row.
// ---------------------------------------------------------------------------
__global__ __launch_bounds__(128) void softmax_kernel()
{
    long row = blockIdx.x;
    float4* p = ((float4*)g_scores) + row * (HW4 / 4);
    int tid  = threadIdx.x;
    int wid  = tid >> 5, lane = tid & 31;

    float4 v0 = p[tid];
    float4 v1 = p[tid + 128];

    float mx = fmaxf(fmaxf(fmaxf(v0.x, v0.y), fmaxf(v0.z, v0.w)),
                     fmaxf(fmaxf(v1.x, v1.y), fmaxf(v1.z, v1.w)));
#pragma unroll
    for (int o = 16; o > 0; o >>= 1)
        mx = fmaxf(mx, __shfl_xor_sync(0xffffffffu, mx, o));

    __shared__ float redm[4];
    __shared__ float reds[4];
    if (lane == 0) redm[wid] = mx;
    __syncthreads();
    mx = fmaxf(fmaxf(redm[0], redm[1]), fmaxf(redm[2], redm[3]));

    v0.x = __expf(v0.x - mx); v0.y = __expf(v0.y - mx);
    v0.z = __expf(v0.z - mx); v0.w = __expf(v0.w - mx);
    v1.x = __expf(v1.x - mx); v1.y = __expf(v1.y - mx);
    v1.z = __expf(v1.z - mx); v1.w = __expf(v1.w - mx);

    float s = v0.x + v0.y + v0.z + v0.w + v1.x + v1.y + v1.z + v1.w;
#pragma unroll
    for (int o = 16; o > 0; o >>= 1)
        s += __shfl_xor_sync(0xffffffffu, s, o);
    if (lane == 0) reds[wid] = s;
    __syncthreads();
    s = reds[0] + reds[1] + reds[2] + reds[3];

    float inv = 1.0f / s;
    v0.x *= inv; v0.y *= inv; v0.z *= inv; v0.w *= inv;
    v1.x *= inv; v1.y *= inv; v1.z *= inv; v1.w *= inv;
    p[tid]       = v0;
    p[tid + 128] = v1;
}

// ---------------------------------------------------------------------------
// Launch
// ---------------------------------------------------------------------------
extern "C" void kernel_launch(void* const* d_in, const int* in_sizes, int n_in,
                              void* d_out, int out_size)
{
    const float* x       = (const float*)d_in[0];
    const float* w_theta = (const float*)d_in[1];
    const float* w_phi   = (const float*)d_in[2];
    const float* w_g     = (const float*)d_in[3];
    const float* w_o     = (const float*)d_in[4];
    const float* gamma   = (const float*)d_in[5];
    float* out = (float*)d_out;

    float *pWall, *pProj, *pPhi, *pG, *pScores, *pY;
    cudaGetSymbolAddress((void**)&pWall,   g_Wall);
    cudaGetSymbolAddress((void**)&pProj,   g_proj);
    cudaGetSymbolAddress((void**)&pPhi,    g_phi);
    cudaGetSymbolAddress((void**)&pG,      g_g);
    cudaGetSymbolAddress((void**)&pScores, g_scores);
    cudaGetSymbolAddress((void**)&pY,      g_y);

    // 1. pack weights
    pack_w_kernel<<<(MPROJ * C_IN + 255) / 256, 256>>>(w_theta, w_phi, w_g);

    // 2. proj = W_all @ x : M=384, N=4096, K=512 (A:N, B:N)
    {
        dim3 grid(HWX / BN, MPROJ / BM, NB);
        gemm_tc<0, 0, 0><<<grid, 256>>>(pWall, x, pProj,
                                        HWX, C_IN, C_IN, HWX,
                                        0, (long)C_IN * HWX, (long)MPROJ * HWX,
                                        nullptr, nullptr, 0);
    }

    // 3. pool phi & g
    {
        long total = (long)NB * 320 * HW4;
        pool_kernel<<<(unsigned)((total + 255) / 256), 256>>>();
    }

    // 4. scores = theta^T @ phi_p : M=4096, N=1024, K=64 (A:T, B:N)
    {
        dim3 grid(HW4 / BN, HWX / BM, NB);
        gemm_tc<1, 0, 0><<<grid, 256>>>(pProj, pPhi, pScores,
                                        HW4, CBAR, HWX, HW4,
                                        (long)MPROJ * HWX, (long)CBAR * HW4,
                                        (long)HWX * HW4,
                                        nullptr, nullptr, 0);
    }

    // 5. softmax rows
    softmax_kernel<<<NB * HWX, 128>>>();

    // 6. y = g_p @ attn^T : M=256, N=4096, K=1024 (A:N, B:T)
    {
        dim3 grid(HWX / BN, CHAT / BM, NB);
        gemm_tc<0, 1, 0><<<grid, 256>>>(pG, pScores, pY,
                                        HWX, HW4, HW4, HW4,
                                        (long)CHAT * HW4, (long)HWX * HW4,
                                        (long)CHAT * HWX,
                                        nullptr, nullptr, 0);
    }

    // 7. out = gamma * (w_o @ y) + x : M=512, N=4096, K=256 (A:N, B:N, EPI)
    {
        dim3 grid(HWX / BN, C_IN / BM, NB);
        gemm_tc<0, 0, 1><<<grid, 256>>>(w_o, pY, out,
                                        HWX, CHAT, CHAT, HWX,
                                        0, (long)CHAT * HWX, (long)C_IN * HWX,
                                        gamma, x, (long)C_IN * HWX);
    }
}

// round 6
// speedup vs baseline: 3.3351x; 1.2592x over previous
#include <cuda_runtime.h>
#include <cuda_bf16.h>

// ---------------------------------------------------------------------------
// SelfAttention2d: N=16, C=512, H=W=64, C_BAR=64, C_HAT=256
// Round 4: flash-fused scores->softmax->y (tf32 QK, bf16 PV).
//   1. pack  W_all[384,512]
//   2. proj[n,384,4096] = W_all @ x_n          (tf32 GEMM)
//   3. pool rows 64..383 -> phi_p[64,1024], g_p[256,1024]
//   4. flash: y[n,256,4096] = g_p @ softmax(theta^T phi_p)^T   (fused)
//   5. out = gamma * (w_o @ y) + x             (tf32 GEMM + epilogue)
// ---------------------------------------------------------------------------

#define NB    16
#define C_IN  512
#define HWX   4096
#define HW4   1024
#define CBAR  64
#define CHAT  256
#define MPROJ 384

#define BM 128
#define BN 128
#define BK 16
#define ASTR 20
#define BSTR 136

// Scratch (static device globals; no allocation at launch time)
__device__ float g_Wall[MPROJ * C_IN];
__device__ float g_proj[(size_t)NB * MPROJ * HWX];
__device__ float g_phi [(size_t)NB * CBAR * HW4];
__device__ float g_g   [(size_t)NB * CHAT * HW4];
__device__ float g_y   [(size_t)NB * CHAT * HWX];

// ---------------------------------------------------------------------------
__device__ __forceinline__ unsigned f2tf(float f) {
    unsigned u;
    asm("cvt.rna.tf32.f32 %0, %1;" : "=r"(u) : "f"(f));
    return u;
}
__device__ __forceinline__ uint4 f2tf4(float4 v) {
    uint4 r; r.x = f2tf(v.x); r.y = f2tf(v.y); r.z = f2tf(v.z); r.w = f2tf(v.w);
    return r;
}
__device__ __forceinline__ void mma_tf32(float d[4], const unsigned a[4],
                                         const unsigned b[2]) {
    asm volatile(
        "mma.sync.aligned.m16n8k8.row.col.f32.tf32.tf32.f32 "
        "{%0,%1,%2,%3}, {%4,%5,%6,%7}, {%8,%9}, {%0,%1,%2,%3};\n"
        : "+f"(d[0]), "+f"(d[1]), "+f"(d[2]), "+f"(d[3])
        : "r"(a[0]), "r"(a[1]), "r"(a[2]), "r"(a[3]), "r"(b[0]), "r"(b[1]));
}
__device__ __forceinline__ void mma_bf16(float d[4], const unsigned a[4],
                                         const unsigned b[2]) {
    asm volatile(
        "mma.sync.aligned.m16n8k16.row.col.f32.bf16.bf16.f32 "
        "{%0,%1,%2,%3}, {%4,%5,%6,%7}, {%8,%9}, {%0,%1,%2,%3};\n"
        : "+f"(d[0]), "+f"(d[1]), "+f"(d[2]), "+f"(d[3])
        : "r"(a[0]), "r"(a[1]), "r"(a[2]), "r"(a[3]), "r"(b[0]), "r"(b[1]));
}

// ---------------------------------------------------------------------------
// Flash attention kernel.
//   Per CTA: batch b = blockIdx.y, queries q0..q0+127 (q0 = blockIdx.x*128).
//   Q = theta^T [4096,64] (from proj rows 0..63), K^T = phi [64,1024],
//   V = g_p^T [1024,256]. 8 KV steps of 128. 512 threads = 16 warps (4x4).
//   QK in tf32, PV in bf16, softmax stats fp32. Writes y[c][q] (c-major).
// ---------------------------------------------------------------------------
#define MQ   128
#define TT   128
#define QSTR 68
#define KSTR 136
#define VSTR 136
#define PSTR 136
#define FLASH_SMEM (34816 + 34816 + 69632 + 34816 + 4096)

__global__ __launch_bounds__(512, 1) void flash_kernel()
{
    extern __shared__ char sm[];
    unsigned*       Qs   = (unsigned*)sm;                       // [128][68] tf32
    unsigned*       Ks   = (unsigned*)(sm + 34816);             // [64][136] tf32
    __nv_bfloat16*  Vs   = (__nv_bfloat16*)(sm + 69632);        // [256][136]
    __nv_bfloat16*  Ps   = (__nv_bfloat16*)(sm + 139264);       // [128][136]
    float*          redm = (float*)(sm + 174080);               // [4][128]
    float*          reds = redm + 512;                          // [4][128]

    const int tid  = threadIdx.x;
    const int lane = tid & 31;
    const int warp = tid >> 5;
    const int g    = lane >> 2;
    const int tig  = lane & 3;
    const int wr   = warp & 3;     // m-tile 0..3 (rows wr*32)
    const int wc   = warp >> 2;    // n-tile 0..3

    const int b  = blockIdx.y;
    const int q0 = blockIdx.x * MQ;

    const float* theta = g_proj + (long)b * MPROJ * HWX;   // rows 0..63
    const float* phi   = g_phi  + (long)b * CBAR * HW4;
    const float* gp    = g_g    + (long)b * CHAT * HW4;
    float*       yp    = g_y    + (long)b * CHAT * HWX;

    // ---- load Q tile (transpose theta[d][q] -> Qs[q][d], tf32), once ----
    for (int i = tid; i < 64 * 32; i += 512) {
        int d = i >> 5, qq = (i & 31) << 2;
        float4 v = *(const float4*)(theta + (long)d * HWX + q0 + qq);
        Qs[(qq + 0) * QSTR + d] = f2tf(v.x);
        Qs[(qq + 1) * QSTR + d] = f2tf(v.y);
        Qs[(qq + 2) * QSTR + d] = f2tf(v.z);
        Qs[(qq + 3) * QSTR + d] = f2tf(v.w);
    }

    float m_run[4], l_run[4];
    float acc_o[2][8][4];
#pragma unroll
    for (int r = 0; r < 4; r++) { m_run[r] = -1e30f; l_run[r] = 0.f; }
#pragma unroll
    for (int mi = 0; mi < 2; mi++)
#pragma unroll
        for (int ni = 0; ni < 8; ni++)
#pragma unroll
            for (int e = 0; e < 4; e++) acc_o[mi][ni][e] = 0.f;

#pragma unroll 1
    for (int j = 0; j < 8; j++) {
        const int t0 = j * TT;
        __syncthreads();   // previous iteration done with Ks/Vs/Ps

        // ---- load K tile: phi[d][t0..] -> Ks[d][t] (tf32, direct) ----
        for (int i = tid; i < 64 * 32; i += 512) {
            int d = i >> 5, tq = (i & 31) << 2;
            float4 v = *(const float4*)(phi + (long)d * HW4 + t0 + tq);
            *(uint4*)&Ks[d * KSTR + tq] = f2tf4(v);
        }
        // ---- load V tile: gp[c][t0..] -> Vs[c][t] (bf16, direct) ----
        for (int i = tid; i < 256 * 32; i += 512) {
            int c = i >> 5, tq = (i & 31) << 2;
            float4 v = *(const float4*)(gp + (long)c * HW4 + t0 + tq);
            *(__nv_bfloat162*)&Vs[c * VSTR + tq]     =
                __float22bfloat162_rn(make_float2(v.x, v.y));
            *(__nv_bfloat162*)&Vs[c * VSTR + tq + 2] =
                __float22bfloat162_rn(make_float2(v.z, v.w));
        }
        __syncthreads();

        // ---- S = Q K^T  (warp tile [32 q] x [32 t], tf32) ----
        float acc_s[2][4][4];
#pragma unroll
        for (int mi = 0; mi < 2; mi++)
#pragma unroll
            for (int ni = 0; ni < 4; ni++)
#pragma unroll
                for (int e = 0; e < 4; e++) acc_s[mi][ni][e] = 0.f;

#pragma unroll
        for (int kd = 0; kd < 64; kd += 8) {
            unsigned af[2][4], bf[4][2];
#pragma unroll
            for (int mi = 0; mi < 2; mi++) {
                int q = wr * 32 + mi * 16 + g;
                af[mi][0] = Qs[q * QSTR + kd + tig];
                af[mi][1] = Qs[(q + 8) * QSTR + kd + tig];
                af[mi][2] = Qs[q * QSTR + kd + tig + 4];
                af[mi][3] = Qs[(q + 8) * QSTR + kd + tig + 4];
            }
#pragma unroll
            for (int ni = 0; ni < 4; ni++) {
                int t = wc * 32 + ni * 8 + g;
                bf[ni][0] = Ks[(kd + tig) * KSTR + t];
                bf[ni][1] = Ks[(kd + tig + 4) * KSTR + t];
            }
#pragma unroll
            for (int mi = 0; mi < 2; mi++)
#pragma unroll
                for (int ni = 0; ni < 4; ni++)
                    mma_tf32(acc_s[mi][ni], af[mi], bf[ni]);
        }

        // ---- row max (thread -> quad -> cross-warp via smem) ----
        float lmax[4];
#pragma unroll
        for (int r = 0; r < 4; r++) lmax[r] = -1e30f;
#pragma unroll
        for (int mi = 0; mi < 2; mi++)
#pragma unroll
            for (int ni = 0; ni < 4; ni++) {
                lmax[mi * 2 + 0] = fmaxf(lmax[mi * 2 + 0],
                                         fmaxf(acc_s[mi][ni][0], acc_s[mi][ni][1]));
                lmax[mi * 2 + 1] = fmaxf(lmax[mi * 2 + 1],
                                         fmaxf(acc_s[mi][ni][2], acc_s[mi][ni][3]));
            }
#pragma unroll
        for (int r = 0; r < 4; r++) {
            lmax[r] = fmaxf(lmax[r], __shfl_xor_sync(0xffffffffu, lmax[r], 1));
            lmax[r] = fmaxf(lmax[r], __shfl_xor_sync(0xffffffffu, lmax[r], 2));
        }
        if (tig == 0) {
#pragma unroll
            for (int r = 0; r < 4; r++) {
                int row = wr * 32 + (r >> 1) * 16 + (r & 1) * 8 + g;
                redm[wc * 128 + row] = lmax[r];
            }
        }
        __syncthreads();

        float corr[4];
#pragma unroll
        for (int r = 0; r < 4; r++) {
            int row = wr * 32 + (r >> 1) * 16 + (r & 1) * 8 + g;
            float mj = fmaxf(fmaxf(redm[row], redm[128 + row]),
                             fmaxf(redm[256 + row], redm[384 + row]));
            float mnew = fmaxf(m_run[r], mj);
            corr[r] = __expf(m_run[r] - mnew);
            m_run[r] = mnew;
        }

        // ---- P = exp(S - m), partial row sums, store P (bf16) ----
        float ls[4] = {0.f, 0.f, 0.f, 0.f};
#pragma unroll
        for (int mi = 0; mi < 2; mi++)
#pragma unroll
            for (int ni = 0; ni < 4; ni++) {
                float p0 = __expf(acc_s[mi][ni][0] - m_run[mi * 2 + 0]);
                float p1 = __expf(acc_s[mi][ni][1] - m_run[mi * 2 + 0]);
                float p2 = __expf(acc_s[mi][ni][2] - m_run[mi * 2 + 1]);
                float p3 = __expf(acc_s[mi][ni][3] - m_run[mi * 2 + 1]);
                ls[mi * 2 + 0] += p0 + p1;
                ls[mi * 2 + 1] += p2 + p3;
                int q = wr * 32 + mi * 16 + g;
                int t = wc * 32 + ni * 8 + 2 * tig;
                *(__nv_bfloat162*)&Ps[q * PSTR + t] =
                    __float22bfloat162_rn(make_float2(p0, p1));
                *(__nv_bfloat162*)&Ps[(q + 8) * PSTR + t] =
                    __float22bfloat162_rn(make_float2(p2, p3));
            }
#pragma unroll
        for (int r = 0; r < 4; r++) {
            ls[r] += __shfl_xor_sync(0xffffffffu, ls[r], 1);
            ls[r] += __shfl_xor_sync(0xffffffffu, ls[r], 2);
        }
        if (tig == 0) {
#pragma unroll
            for (int r = 0; r < 4; r++) {
                int row = wr * 32 + (r >> 1) * 16 + (r & 1) * 8 + g;
                reds[wc * 128 + row] = ls[r];
            }
        }
        __syncthreads();

#pragma unroll
        for (int r = 0; r < 4; r++) {
            int row = wr * 32 + (r >> 1) * 16 + (r & 1) * 8 + g;
            float lj = reds[row] + reds[128 + row] + reds[256 + row] + reds[384 + row];
            l_run[r] = l_run[r] * corr[r] + lj;
        }
        // rescale O accumulators
#pragma unroll
        for (int mi = 0; mi < 2; mi++)
#pragma unroll
            for (int ni = 0; ni < 8; ni++) {
                acc_o[mi][ni][0] *= corr[mi * 2 + 0];
                acc_o[mi][ni][1] *= corr[mi * 2 + 0];
                acc_o[mi][ni][2] *= corr[mi * 2 + 1];
                acc_o[mi][ni][3] *= corr[mi * 2 + 1];
            }

        // ---- O += P V  (warp tile [32 q] x [64 c], bf16) ----
#pragma unroll
        for (int kt = 0; kt < TT; kt += 16) {
            unsigned pa[2][4];
#pragma unroll
            for (int mi = 0; mi < 2; mi++) {
                int q = wr * 32 + mi * 16 + g;
                pa[mi][0] = *(const unsigned*)&Ps[q * PSTR + kt + 2 * tig];
                pa[mi][1] = *(const unsigned*)&Ps[(q + 8) * PSTR + kt + 2 * tig];
                pa[mi][2] = *(const unsigned*)&Ps[q * PSTR + kt + 8 + 2 * tig];
                pa[mi][3] = *(const unsigned*)&Ps[(q + 8) * PSTR + kt + 8 + 2 * tig];
            }
#pragma unroll
            for (int ni = 0; ni < 8; ni++) {
                int c = wc * 64 + ni * 8 + g;
                unsigned vb[2];
                vb[0] = *(const unsigned*)&Vs[c * VSTR + kt + 2 * tig];
                vb[1] = *(const unsigned*)&Vs[c * VSTR + kt + 8 + 2 * tig];
                mma_bf16(acc_o[0][ni], pa[0], vb);
                mma_bf16(acc_o[1][ni], pa[1], vb);
            }
        }
    }

    // ---- epilogue: y[c][q] = O[q][c] / l ----
    float inv[4];
#pragma unroll
    for (int r = 0; r < 4; r++) inv[r] = 1.0f / l_run[r];

#pragma unroll
    for (int mi = 0; mi < 2; mi++) {
        int q = q0 + wr * 32 + mi * 16 + g;
#pragma unroll
        for (int ni = 0; ni < 8; ni++) {
            int c = wc * 64 + ni * 8 + 2 * tig;
            yp[(long)c * HWX + q]           = acc_o[mi][ni][0] * inv[mi * 2 + 0];
            yp[(long)(c + 1) * HWX + q]     = acc_o[mi][ni][1] * inv[mi * 2 + 0];
            yp[(long)c * HWX + q + 8]       = acc_o[mi][ni][2] * inv[mi * 2 + 1];
            yp[(long)(c + 1) * HWX + q + 8] = acc_o[mi][ni][3] * inv[mi * 2 + 1];
        }
    }
}

// ---------------------------------------------------------------------------
// Templated tf32 GEMM (NN only now): C = A @ B (+ gamma/residual epilogue)
// ---------------------------------------------------------------------------
template<int EPI>
__global__ __launch_bounds__(256, 2) void gemm_tc(
    const float* __restrict__ A, const float* __restrict__ B,
    float* __restrict__ C,
    int N, int K, int lda, int ldb,
    long sA, long sB, long sC,
    const float* __restrict__ gammaPtr,
    const float* __restrict__ resid, long sR)
{
    __shared__ __align__(16) unsigned As[2][BM][ASTR];
    __shared__ __align__(16) unsigned Bs[2][BK][BSTR];

    const int tid  = threadIdx.x;
    const int lane = tid & 31;
    const int warp = tid >> 5;
    const int g    = lane >> 2;
    const int tig  = lane & 3;
    const int wm   = (warp & 1) * 64;
    const int wn   = (warp >> 1) * 32;

    const int b  = blockIdx.z;
    const int m0 = blockIdx.y * BM;
    const int n0 = blockIdx.x * BN;

    const float* Ap = A + (long)b * sA;
    const float* Bp = B + (long)b * sB;
    float*       Cp = C + (long)b * sC;

    float acc[4][4][4];
#pragma unroll
    for (int i = 0; i < 4; i++)
#pragma unroll
        for (int j = 0; j < 4; j++)
#pragma unroll
            for (int r = 0; r < 4; r++) acc[i][j][r] = 0.f;

    float4 ra0, ra1, rb0, rb1;

    auto loadA = [&](int k0) {
        int m = tid >> 2, kq = (tid & 3) << 2;
        ra0 = *(const float4*)(Ap + (long)(m0 + m)      * lda + k0 + kq);
        ra1 = *(const float4*)(Ap + (long)(m0 + m + 64) * lda + k0 + kq);
    };
    auto loadB = [&](int k0) {
        int k = tid >> 5, n = (tid & 31) << 2;
        rb0 = *(const float4*)(Bp + (long)(k0 + k)     * ldb + n0 + n);
        rb1 = *(const float4*)(Bp + (long)(k0 + k + 8) * ldb + n0 + n);
    };
    auto storeAB = [&](int buf) {
        int m = tid >> 2, kq = (tid & 3) << 2;
        *(uint4*)&As[buf][m][kq]      = f2tf4(ra0);
        *(uint4*)&As[buf][m + 64][kq] = f2tf4(ra1);
        int k = tid >> 5, n = (tid & 31) << 2;
        int s0 = ((k >> 2) & 3) << 3;
        int s1 = (((k + 8) >> 2) & 3) << 3;
        *(uint4*)&Bs[buf][k][n ^ s0]     = f2tf4(rb0);
        *(uint4*)&Bs[buf][k + 8][n ^ s1] = f2tf4(rb1);
    };
    auto compute = [&](int buf) {
#pragma unroll
        for (int ks = 0; ks < BK; ks += 8) {
            unsigned af[4][4], bf[4][2];
            const int s0 = ((ks >> 2) & 3) << 3;
            const int s1 = (((ks >> 2) + 1) & 3) << 3;
#pragma unroll
            for (int mi = 0; mi < 4; mi++) {
                int m = wm + mi * 16;
                af[mi][0] = As[buf][m + g]    [ks + tig];
                af[mi][1] = As[buf][m + g + 8][ks + tig];
                af[mi][2] = As[buf][m + g]    [ks + tig + 4];
                af[mi][3] = As[buf][m + g + 8][ks + tig + 4];
            }
#pragma unroll
            for (int ni = 0; ni < 4; ni++) {
                int n = wn + ni * 8 + g;
                bf[ni][0] = Bs[buf][ks + tig]    [n ^ s0];
                bf[ni][1] = Bs[buf][ks + tig + 4][n ^ s1];
            }
#pragma unroll
            for (int mi = 0; mi < 4; mi++)
#pragma unroll
                for (int ni = 0; ni < 4; ni++)
                    mma_tf32(acc[mi][ni], af[mi], bf[ni]);
        }
    };

    const int nt = K / BK;
    loadA(0); loadB(0);
    storeAB(0);
    __syncthreads();
#pragma unroll 1
    for (int t = 0; t < nt; t++) {
        if (t + 1 < nt) { loadA((t + 1) * BK); loadB((t + 1) * BK); }
        compute(t & 1);
        if (t + 1 < nt) storeAB((t + 1) & 1);
        __syncthreads();
    }

    float gam = 0.f;
    const float* Rp = nullptr;
    if (EPI) { gam = gammaPtr[0]; Rp = resid + (long)b * sR; }

#pragma unroll
    for (int mi = 0; mi < 4; mi++) {
#pragma unroll
        for (int ni = 0; ni < 4; ni++) {
            int m = m0 + wm + mi * 16 + g;
            int n = n0 + wn + ni * 8 + 2 * tig;
            float2 v0 = make_float2(acc[mi][ni][0], acc[mi][ni][1]);
            float2 v1 = make_float2(acc[mi][ni][2], acc[mi][ni][3]);
            if (EPI) {
                float2 r0 = *(const float2*)(Rp + (long)m * N + n);
                float2 r1 = *(const float2*)(Rp + (long)(m + 8) * N + n);
                v0.x = fmaf(gam, v0.x, r0.x);
                v0.y = fmaf(gam, v0.y, r0.y);
                v1.x = fmaf(gam, v1.x, r1.x);
                v1.y = fmaf(gam, v1.y, r1.y);
            }
            *(float2*)(Cp + (long)m * N + n)       = v0;
            *(float2*)(Cp + (long)(m + 8) * N + n) = v1;
        }
    }
}

// ---------------------------------------------------------------------------
__global__ void pack_w_kernel(const float* __restrict__ wt,
                              const float* __restrict__ wp,
                              const float* __restrict__ wg)
{
    int i = blockIdx.x * blockDim.x + threadIdx.x;
    if (i >= MPROJ * C_IN) return;
    const int T = 64 * C_IN;
    const int P = 128 * C_IN;
    float v;
    if (i < T)       v = wt[i];
    else if (i < P)  v = wp[i - T];
    else             v = wg[i - P];
    g_Wall[i] = v;
}

__global__ void pool_kernel()
{
    long idx = (long)blockIdx.x * blockDim.x + threadIdx.x;
    const long total = (long)NB * 320 * HW4;
    if (idx >= total) return;
    int  tp = (int)(idx & (HW4 - 1));
    long rest = idx >> 10;
    int  ch = (int)(rest % 320);
    int  b  = (int)(rest / 320);
    int  ph = tp >> 5, pw = tp & 31;

    int srcRow = (ch < CBAR) ? (64 + ch) : (128 + (ch - CBAR));
    const float* src = g_proj + (long)b * MPROJ * HWX
                              + (long)srcRow * HWX
                              + (2 * ph) * 64 + 2 * pw;
    float m = fmaxf(fmaxf(src[0], src[1]), fmaxf(src[64], src[65]));

    if (ch < CBAR)
        g_phi[((long)b * CBAR + ch) * HW4 + tp] = m;
    else
        g_g[((long)b * CHAT + (ch - CBAR)) * HW4 + tp] = m;
}

// ---------------------------------------------------------------------------
extern "C" void kernel_launch(void* const* d_in, const int* in_sizes, int n_in,
                              void* d_out, int out_size)
{
    const float* x       = (const float*)d_in[0];
    const float* w_theta = (const float*)d_in[1];
    const float* w_phi   = (const float*)d_in[2];
    const float* w_g     = (const float*)d_in[3];
    const float* w_o     = (const float*)d_in[4];
    const float* gamma   = (const float*)d_in[5];
    float* out = (float*)d_out;

    float *pWall, *pProj, *pY;
    cudaGetSymbolAddress((void**)&pWall, g_Wall);
    cudaGetSymbolAddress((void**)&pProj, g_proj);
    cudaGetSymbolAddress((void**)&pY,    g_y);

    static int smem_set = 0;
    if (!smem_set) {
        cudaFuncSetAttribute(flash_kernel,
                             cudaFuncAttributeMaxDynamicSharedMemorySize,
                             FLASH_SMEM);
        smem_set = 1;
    }

    // 1. pack weights
    pack_w_kernel<<<(MPROJ * C_IN + 255) / 256, 256>>>(w_theta, w_phi, w_g);

    // 2. proj = W_all @ x : M=384, N=4096, K=512
    {
        dim3 grid(HWX / BN, MPROJ / BM, NB);
        gemm_tc<0><<<grid, 256>>>(pWall, x, pProj,
                                  HWX, C_IN, C_IN, HWX,
                                  0, (long)C_IN * HWX, (long)MPROJ * HWX,
                                  nullptr, nullptr, 0);
    }

    // 3. pool phi & g
    {
        long total = (long)NB * 320 * HW4;
        pool_kernel<<<(unsigned)((total + 255) / 256), 256>>>();
    }

    // 4. flash: fused scores -> softmax -> y
    {
        dim3 grid(HWX / MQ, NB);
        flash_kernel<<<grid, 512, FLASH_SMEM>>>();
    }

    // 5. out = gamma * (w_o @ y) + x : M=512, N=4096, K=256
    {
        dim3 grid(HWX / BN, C_IN / BM, NB);
        gemm_tc<1><<<grid, 256>>>(w_o, pY, out,
                                  HWX, CHAT, CHAT, HWX,
                                  0, (long)CHAT * HWX, (long)C_IN * HWX,
                                  gamma, x, (long)C_IN * HWX);
    }
}